// round 10
// baseline (speedup 1.0000x reference)
#include <cuda_runtime.h>
#include <math.h>
#include <stdint.h>

#define NN 100000
#define EE 600000
#define DIN 256
#define DH  128
#define DE  64
#define NB  ((NN + 1023) / 1024)

// ---------------- scratch (static device globals; no allocation) ------------
__device__ float g_h   [(size_t)NN * DH];  // GEMM output (pre-aggregation)
__device__ float g_h1  [(size_t)NN * DH];  // layer activation buffer
__device__ float g_din [NN];               // 1/sqrt(deg+1)
__device__ int   g_cnt [NN];               // in-degree counts
__device__ int   g_rowptr[NN + 1];         // CSR row pointers (by dst)
__device__ int   g_cur [NN];               // placement cursors
__device__ int   g_bsum[NB];               // scan block sums
__device__ int   g_ssrc [EE];              // CSR: src node per sorted edge
__device__ float g_scoef[EE];              // CSR: dinv[src]*dinv[dst]
__device__ int   g_src[EE];
__device__ int   g_dst[EE];
__device__ int   g_is64;

__device__ __forceinline__ float* bufptr(int id) {
    switch (id) {
        case 0:  return g_h;
        default: return g_h1;
    }
}

// ---------------- edge-index dtype detection + conversion -------------------
__global__ void detect_kernel(const int* __restrict__ w) {
    if (threadIdx.x == 0 && blockIdx.x == 0) {
        int is64 = 1;
        for (int i = 1; i < 128; i += 2)
            if (w[i] != 0) { is64 = 0; break; }
        g_is64 = is64;
    }
}

// convert + clamp + count in-degree (dst side) in one pass
__global__ void convert_kernel(const void* __restrict__ ei) {
    int e = blockIdx.x * blockDim.x + threadIdx.x;
    if (e >= 2 * EE) return;
    int v;
    if (g_is64) v = (int)((const long long*)ei)[e];
    else        v = ((const int*)ei)[e];
    v = max(0, min(NN - 1, v));
    if (e < EE) g_src[e] = v;
    else        { g_dst[e - EE] = v; atomicAdd(&g_cnt[v], 1); }
}

// ---------------- CSR construction -------------------------------------------
__global__ void zero_cnt_kernel() {
    int i = blockIdx.x * blockDim.x + threadIdx.x;
    if (i < NN) g_cnt[i] = 0;
}

// scan of counts -> rowptr[i+1]; also computes dinv (fused)
__global__ void scan1_kernel() {
    __shared__ int s[1024];
    int i = blockIdx.x * 1024 + threadIdx.x;
    int v = (i < NN) ? g_cnt[i] : 0;
    if (i < NN) g_din[i] = rsqrtf((float)v + 1.0f);
    s[threadIdx.x] = v;
    __syncthreads();
    for (int off = 1; off < 1024; off <<= 1) {
        int t = (threadIdx.x >= off) ? s[threadIdx.x - off] : 0;
        __syncthreads();
        s[threadIdx.x] += t;
        __syncthreads();
    }
    if (i < NN) g_rowptr[i + 1] = s[threadIdx.x];
    if (threadIdx.x == 1023) g_bsum[blockIdx.x] = s[1023];
}

__global__ void scan2_kernel() {
    if (threadIdx.x == 0 && blockIdx.x == 0) {
        int run = 0;
        for (int b = 0; b < NB; b++) { int t = g_bsum[b]; g_bsum[b] = run; run += t; }
        g_rowptr[0] = 0;
    }
}

// finalize rowptr, init cursors (fused: cur[i] = rowptr[i+1]-cnt[i])
__global__ void scan3_kernel() {
    int i = blockIdx.x * blockDim.x + threadIdx.x;
    if (i < NN) {
        int v = g_rowptr[i + 1] + g_bsum[i >> 10];
        g_rowptr[i + 1] = v;
        g_cur[i] = v - g_cnt[i];
    }
}

__global__ void fill_csr_kernel() {
    int e = blockIdx.x * blockDim.x + threadIdx.x;
    if (e >= EE) return;
    int s = g_src[e];
    int d = g_dst[e];
    int slot = atomicAdd(&g_cur[d], 1);
    g_ssrc[slot]  = s;
    g_scoef[slot] = g_din[s] * g_din[d];
}

// ---------------- fused aggregation (gather + self-loop + bias + relu) -------
__global__ void agg_d128_kernel(const float* __restrict__ bias,
                                float* out_ext, int out_id, int do_relu) {
    int warp = (blockIdx.x * blockDim.x + threadIdx.x) >> 5;
    int lane = threadIdx.x & 31;
    if (warp >= NN) return;
    float* out = out_ext ? out_ext : bufptr(out_id);
    int rs = g_rowptr[warp], re = g_rowptr[warp + 1];
    float di = g_din[warp];
    float sc = di * di;
    float4 acc = *reinterpret_cast<const float4*>(g_h + (size_t)warp * 128 + lane * 4);
    acc.x *= sc; acc.y *= sc; acc.z *= sc; acc.w *= sc;
    for (int j = rs; j < re; j++) {
        int s = g_ssrc[j];
        float c = g_scoef[j];
        float4 v = *reinterpret_cast<const float4*>(g_h + (size_t)s * 128 + lane * 4);
        acc.x += v.x * c; acc.y += v.y * c; acc.z += v.z * c; acc.w += v.w * c;
    }
    float4 b = *reinterpret_cast<const float4*>(bias + lane * 4);
    acc.x += b.x; acc.y += b.y; acc.z += b.z; acc.w += b.w;
    if (do_relu) {
        acc.x = fmaxf(acc.x, 0.0f); acc.y = fmaxf(acc.y, 0.0f);
        acc.z = fmaxf(acc.z, 0.0f); acc.w = fmaxf(acc.w, 0.0f);
    }
    *reinterpret_cast<float4*>(out + (size_t)warp * 128 + lane * 4) = acc;
}

__global__ void agg_d64_kernel(const float* __restrict__ bias,
                               float* out_ext, int out_id, int do_relu) {
    int warp = (blockIdx.x * blockDim.x + threadIdx.x) >> 5;
    int lane = threadIdx.x & 31;
    if (warp >= NN) return;
    float* out = out_ext ? out_ext : bufptr(out_id);
    int rs = g_rowptr[warp], re = g_rowptr[warp + 1];
    float di = g_din[warp];
    float sc = di * di;
    float2 acc = *reinterpret_cast<const float2*>(g_h + (size_t)warp * 64 + lane * 2);
    acc.x *= sc; acc.y *= sc;
    for (int j = rs; j < re; j++) {
        int s = g_ssrc[j];
        float c = g_scoef[j];
        float2 v = *reinterpret_cast<const float2*>(g_h + (size_t)s * 64 + lane * 2);
        acc.x += v.x * c; acc.y += v.y * c;
    }
    float2 b = *reinterpret_cast<const float2*>(bias + lane * 2);
    acc.x += b.x; acc.y += b.y;
    if (do_relu) { acc.x = fmaxf(acc.x, 0.0f); acc.y = fmaxf(acc.y, 0.0f); }
    *reinterpret_cast<float2*>(out + (size_t)warp * 64 + lane * 2) = acc;
}

// ---------------- TF32x3 tensor-core GEMM ------------------------------------
// C[N,M] = A[N,K] @ B[K,M] (+bias)(+relu)
// block tile 128x64, 8 warps (4 m x 2 n), warp tile 32x32, BK=16.
// hi/lo tf32 interleaved as uint2 in smem -> one LDS.64 per fragment element.
// Combo-outermost mma ordering (HH, HL, LH) keeps accumulator reuse distance 8.
#define GBM 128
#define GBN 64
#define GBK 16
#define APAD 4    // A stride 20 uint2: 2-way on 64-bit loads (bandwidth-optimal)
#define BPAD 8    // B stride 72 uint2: 2-way on 64-bit loads

__device__ __forceinline__ uint32_t f2tf32(float f) {
    uint32_t u;
    asm("cvt.rna.tf32.f32 %0, %1;" : "=r"(u) : "f"(f));
    return u;
}

__device__ __forceinline__ uint2 splitp(float f) {
    uint2 p;
    p.x = f2tf32(f);
    p.y = f2tf32(f - __uint_as_float(p.x));
    return p;
}

// non-volatile, no clobbers: lets ptxas interleave independent mmas
__device__ __forceinline__ void mma_tf32(float c[4],
                                         uint32_t a0, uint32_t a1, uint32_t a2, uint32_t a3,
                                         uint32_t b0, uint32_t b1) {
    asm("mma.sync.aligned.m16n8k8.row.col.f32.tf32.tf32.f32 "
        "{%0,%1,%2,%3}, {%4,%5,%6,%7}, {%8,%9}, {%0,%1,%2,%3};"
        : "+f"(c[0]), "+f"(c[1]), "+f"(c[2]), "+f"(c[3])
        : "r"(a0), "r"(a1), "r"(a2), "r"(a3), "r"(b0), "r"(b1));
}

__global__ void __launch_bounds__(256, 2)
gemm_tc_kernel(const float* A_ext, int a_id,
               const float* __restrict__ B,
               const float* __restrict__ bias,
               float* C_ext, int c_id,
               int N, int K, int M, int do_relu) {
    __shared__ uint2 AsP[GBM][GBK + APAD];   // .x = hi, .y = lo
    __shared__ uint2 BsP[GBK][GBN + BPAD];

    const float* A = A_ext ? A_ext : bufptr(a_id);
    float*       C = C_ext ? C_ext : bufptr(c_id);

    int tid  = threadIdx.x;
    int wid  = tid >> 5;
    int lane = tid & 31;
    int wm   = wid & 3;
    int wn   = wid >> 2;
    int group = lane >> 2;       // 0..7
    int tig   = lane & 3;        // 0..3

    int row0 = blockIdx.y * GBM;
    int col0 = blockIdx.x * GBN;

    float acc[2][4][4];
#pragma unroll
    for (int mi = 0; mi < 2; mi++)
#pragma unroll
        for (int ni = 0; ni < 4; ni++)
#pragma unroll
            for (int q = 0; q < 4; q++) acc[mi][ni][q] = 0.0f;

    auto loadTile = [&](int k0, float4 (&pa)[2], float4& pb) {
#pragma unroll
        for (int q = 0; q < 2; q++) {
            int f4 = tid * 2 + q;
            int r  = f4 >> 2;
            int c4 = (f4 & 3) * 4;
            int gr = row0 + r;
            pa[q] = (gr < N)
                  ? *reinterpret_cast<const float4*>(A + (size_t)gr * K + k0 + c4)
                  : make_float4(0.f, 0.f, 0.f, 0.f);
        }
        {
            int r  = tid >> 4;
            int c4 = (tid & 15) * 4;
            pb = *reinterpret_cast<const float4*>(B + (size_t)(k0 + r) * M + col0 + c4);
        }
    };

    auto storeTile = [&](const float4 (&pa)[2], const float4& pb) {
#pragma unroll
        for (int q = 0; q < 2; q++) {
            int f4 = tid * 2 + q;
            int r  = f4 >> 2;
            int c4 = (f4 & 3) * 4;
            AsP[r][c4 + 0] = splitp(pa[q].x);
            AsP[r][c4 + 1] = splitp(pa[q].y);
            AsP[r][c4 + 2] = splitp(pa[q].z);
            AsP[r][c4 + 3] = splitp(pa[q].w);
        }
        {
            int r  = tid >> 4;
            int c4 = (tid & 15) * 4;
            BsP[r][c4 + 0] = splitp(pb.x);
            BsP[r][c4 + 1] = splitp(pb.y);
            BsP[r][c4 + 2] = splitp(pb.z);
            BsP[r][c4 + 3] = splitp(pb.w);
        }
    };

    auto compute = [&]() {
#pragma unroll
        for (int kk = 0; kk < GBK; kk += 8) {
            uint2 a[2][4];      // [mi][frag], .x=hi .y=lo
            uint2 b[4][2];      // [ni][frag]
#pragma unroll
            for (int mi = 0; mi < 2; mi++) {
                int m = wm * 32 + mi * 16 + group;
                a[mi][0] = AsP[m    ][kk + tig];
                a[mi][1] = AsP[m + 8][kk + tig];
                a[mi][2] = AsP[m    ][kk + tig + 4];
                a[mi][3] = AsP[m + 8][kk + tig + 4];
            }
#pragma unroll
            for (int ni = 0; ni < 4; ni++) {
                int n = wn * 32 + ni * 8 + group;
                b[ni][0] = BsP[kk + tig    ][n];
                b[ni][1] = BsP[kk + tig + 4][n];
            }
            // pass 1: HH over all 8 independent accumulators
#pragma unroll
            for (int ni = 0; ni < 4; ni++)
#pragma unroll
                for (int mi = 0; mi < 2; mi++)
                    mma_tf32(acc[mi][ni], a[mi][0].x, a[mi][1].x, a[mi][2].x, a[mi][3].x,
                             b[ni][0].x, b[ni][1].x);
            // pass 2: HL
#pragma unroll
            for (int ni = 0; ni < 4; ni++)
#pragma unroll
                for (int mi = 0; mi < 2; mi++)
                    mma_tf32(acc[mi][ni], a[mi][0].x, a[mi][1].x, a[mi][2].x, a[mi][3].x,
                             b[ni][0].y, b[ni][1].y);
            // pass 3: LH
#pragma unroll
            for (int ni = 0; ni < 4; ni++)
#pragma unroll
                for (int mi = 0; mi < 2; mi++)
                    mma_tf32(acc[mi][ni], a[mi][0].y, a[mi][1].y, a[mi][2].y, a[mi][3].y,
                             b[ni][0].x, b[ni][1].x);
        }
    };

    // prologue: tile 0
    float4 pa[2]; float4 pb;
    loadTile(0, pa, pb);
    storeTile(pa, pb);
    __syncthreads();

    // main loop with register prefetch
    for (int k0 = GBK; k0 < K; k0 += GBK) {
        float4 na[2]; float4 nb;
        loadTile(k0, na, nb);        // prefetch next tile (gmem -> regs)
        compute();                   // compute current tile from smem
        __syncthreads();
        storeTile(na, nb);           // split + store prefetched tile
        __syncthreads();
    }
    compute();                       // last tile

    // ---- epilogue ----
#pragma unroll
    for (int mi = 0; mi < 2; mi++) {
#pragma unroll
        for (int ni = 0; ni < 4; ni++) {
            int colb = col0 + wn * 32 + ni * 8 + tig * 2;
            float b0 = 0.f, b1 = 0.f;
            if (bias) { b0 = bias[colb]; b1 = bias[colb + 1]; }
#pragma unroll
            for (int half = 0; half < 2; half++) {
                int r = row0 + wm * 32 + mi * 16 + group + half * 8;
                if (r >= N) continue;
                float v0 = acc[mi][ni][half * 2 + 0] + b0;
                float v1 = acc[mi][ni][half * 2 + 1] + b1;
                if (do_relu) { v0 = fmaxf(v0, 0.f); v1 = fmaxf(v1, 0.f); }
                float2 vv = make_float2(v0, v1);
                *reinterpret_cast<float2*>(C + (size_t)r * M + colb) = vv;
            }
        }
    }
}

// ---------------- orchestration ----------------------------------------------
static inline void run_gemm(const float* A_ext, int a_id, const float* B,
                            const float* bias, float* C_ext, int c_id,
                            int n, int K, int M, int relu) {
    dim3 grid(M / GBN, (n + GBM - 1) / GBM);
    gemm_tc_kernel<<<grid, 256>>>(A_ext, a_id, B, bias, C_ext, c_id, n, K, M, relu);
}

static inline void run_agg128(const float* b, float* out_ext, int out_id, int relu) {
    int blocks = (NN + 7) / 8;
    agg_d128_kernel<<<blocks, 256>>>(b, out_ext, out_id, relu);
}

static inline void run_agg64(const float* b, float* out_ext, int out_id, int relu) {
    int blocks = (NN + 7) / 8;
    agg_d64_kernel<<<blocks, 256>>>(b, out_ext, out_id, relu);
}

extern "C" void kernel_launch(void* const* d_in, const int* in_sizes, int n_in,
                              void* d_out, int out_size) {
    const float* x   = (const float*)d_in[0];
    const void*  ei  = d_in[1];
    const float* W1  = (const float*)d_in[2];
    const float* b1  = (const float*)d_in[3];
    const float* W2  = (const float*)d_in[4];
    const float* b2  = (const float*)d_in[5];
    const float* W3  = (const float*)d_in[6];
    const float* b3  = (const float*)d_in[7];
    const float* Wd1 = (const float*)d_in[8];
    const float* bd1 = (const float*)d_in[9];
    const float* Wd2 = (const float*)d_in[10];
    const float* bd2 = (const float*)d_in[11];

    float* z    = (float*)d_out;                     // [N, 64]
    float* xhat = (float*)d_out + (size_t)NN * DE;   // [N, 256]

    // ---- graph preprocessing: dtype convert + CSR build -----------------
    detect_kernel<<<1, 32>>>((const int*)ei);
    zero_cnt_kernel<<<(NN + 255) / 256, 256>>>();
    convert_kernel<<<(2 * EE + 255) / 256, 256>>>(ei);
    scan1_kernel<<<NB, 1024>>>();                       // scan + dinv (fused)
    scan2_kernel<<<1, 32>>>();
    scan3_kernel<<<(NN + 255) / 256, 256>>>();          // rowptr final + cur (fused)
    fill_csr_kernel<<<(EE + 255) / 256, 256>>>();

    // ---- layer 1: h1 = relu(gcn(x, W1, b1)) -----------------------------
    run_gemm(x, -1, W1, nullptr, nullptr, 0, NN, DIN, DH, 0);   // g_h = x@W1
    run_agg128(b1, nullptr, 2, 1);                              // -> g_h1

    // ---- layer 2: h2 = relu(gcn(h1, W2, b2)) ----------------------------
    run_gemm(nullptr, 2, W2, nullptr, nullptr, 0, NN, DH, DH, 0);
    run_agg128(b2, nullptr, 2, 1);

    // ---- layer 3: z = gcn(h2, W3, b3) -----------------------------------
    run_gemm(nullptr, 2, W3, nullptr, nullptr, 0, NN, DH, DE, 0);
    run_agg64(b3, z, -1, 0);

    // ---- decoder: x_hat = relu(z@Wd1+bd1)@Wd2 + bd2 ---------------------
    run_gemm(z, -1, Wd1, bd1, nullptr, 2, NN, DE, DH, 1);
    run_gemm(nullptr, 2, Wd2, bd2, xhat, -1, NN, DH, DIN, 0);
}

// round 11
// speedup vs baseline: 1.5841x; 1.5841x over previous
#include <cuda_runtime.h>
#include <cuda_bf16.h>
#include <math.h>
#include <stdint.h>

#define NN 100000
#define EE 600000
#define DIN 256
#define DH  128
#define DE  64
#define NB  ((NN + 1023) / 1024)

// ---------------- scratch (static device globals; no allocation) ------------
__device__ float g_h   [(size_t)NN * DH];  // GEMM output (pre-aggregation)
__device__ float g_h1  [(size_t)NN * DH];  // layer activation buffer
__device__ float g_din [NN];               // 1/sqrt(deg+1)
__device__ int   g_cnt [NN];               // in-degree counts
__device__ int   g_rowptr[NN + 1];         // CSR row pointers (by dst)
__device__ int   g_cur [NN];               // placement cursors
__device__ int   g_bsum[NB];               // scan block sums
__device__ int   g_ssrc [EE];              // CSR: src node per sorted edge
__device__ float g_scoef[EE];              // CSR: dinv[src]*dinv[dst]
__device__ int   g_src[EE];
__device__ int   g_dst[EE];
__device__ int   g_is64;

__device__ __forceinline__ float* bufptr(int id) {
    switch (id) {
        case 0:  return g_h;
        default: return g_h1;
    }
}

// ---------------- edge-index dtype detection + conversion -------------------
__global__ void detect_kernel(const int* __restrict__ w) {
    if (threadIdx.x == 0 && blockIdx.x == 0) {
        int is64 = 1;
        for (int i = 1; i < 128; i += 2)
            if (w[i] != 0) { is64 = 0; break; }
        g_is64 = is64;
    }
}

// convert + clamp + count in-degree (dst side) in one pass
__global__ void convert_kernel(const void* __restrict__ ei) {
    int e = blockIdx.x * blockDim.x + threadIdx.x;
    if (e >= 2 * EE) return;
    int v;
    if (g_is64) v = (int)((const long long*)ei)[e];
    else        v = ((const int*)ei)[e];
    v = max(0, min(NN - 1, v));
    if (e < EE) g_src[e] = v;
    else        { g_dst[e - EE] = v; atomicAdd(&g_cnt[v], 1); }
}

// ---------------- CSR construction -------------------------------------------
__global__ void zero_cnt_kernel() {
    int i = blockIdx.x * blockDim.x + threadIdx.x;
    if (i < NN) g_cnt[i] = 0;
}

// scan of counts -> rowptr[i+1]; also computes dinv (fused)
__global__ void scan1_kernel() {
    __shared__ int s[1024];
    int i = blockIdx.x * 1024 + threadIdx.x;
    int v = (i < NN) ? g_cnt[i] : 0;
    if (i < NN) g_din[i] = rsqrtf((float)v + 1.0f);
    s[threadIdx.x] = v;
    __syncthreads();
    for (int off = 1; off < 1024; off <<= 1) {
        int t = (threadIdx.x >= off) ? s[threadIdx.x - off] : 0;
        __syncthreads();
        s[threadIdx.x] += t;
        __syncthreads();
    }
    if (i < NN) g_rowptr[i + 1] = s[threadIdx.x];
    if (threadIdx.x == 1023) g_bsum[blockIdx.x] = s[1023];
}

__global__ void scan2_kernel() {
    if (threadIdx.x == 0 && blockIdx.x == 0) {
        int run = 0;
        for (int b = 0; b < NB; b++) { int t = g_bsum[b]; g_bsum[b] = run; run += t; }
        g_rowptr[0] = 0;
    }
}

// finalize rowptr, init cursors (fused: cur[i] = rowptr[i+1]-cnt[i])
__global__ void scan3_kernel() {
    int i = blockIdx.x * blockDim.x + threadIdx.x;
    if (i < NN) {
        int v = g_rowptr[i + 1] + g_bsum[i >> 10];
        g_rowptr[i + 1] = v;
        g_cur[i] = v - g_cnt[i];
    }
}

__global__ void fill_csr_kernel() {
    int e = blockIdx.x * blockDim.x + threadIdx.x;
    if (e >= EE) return;
    int s = g_src[e];
    int d = g_dst[e];
    int slot = atomicAdd(&g_cur[d], 1);
    g_ssrc[slot]  = s;
    g_scoef[slot] = g_din[s] * g_din[d];
}

// ---------------- fused aggregation (gather + self-loop + bias + relu) -------
__global__ void agg_d128_kernel(const float* __restrict__ bias,
                                float* out_ext, int out_id, int do_relu) {
    int warp = (blockIdx.x * blockDim.x + threadIdx.x) >> 5;
    int lane = threadIdx.x & 31;
    if (warp >= NN) return;
    float* out = out_ext ? out_ext : bufptr(out_id);
    int rs = g_rowptr[warp], re = g_rowptr[warp + 1];
    float di = g_din[warp];
    float sc = di * di;
    float4 acc = *reinterpret_cast<const float4*>(g_h + (size_t)warp * 128 + lane * 4);
    acc.x *= sc; acc.y *= sc; acc.z *= sc; acc.w *= sc;
    for (int j = rs; j < re; j++) {
        int s = g_ssrc[j];
        float c = g_scoef[j];
        float4 v = *reinterpret_cast<const float4*>(g_h + (size_t)s * 128 + lane * 4);
        acc.x += v.x * c; acc.y += v.y * c; acc.z += v.z * c; acc.w += v.w * c;
    }
    float4 b = *reinterpret_cast<const float4*>(bias + lane * 4);
    acc.x += b.x; acc.y += b.y; acc.z += b.z; acc.w += b.w;
    if (do_relu) {
        acc.x = fmaxf(acc.x, 0.0f); acc.y = fmaxf(acc.y, 0.0f);
        acc.z = fmaxf(acc.z, 0.0f); acc.w = fmaxf(acc.w, 0.0f);
    }
    *reinterpret_cast<float4*>(out + (size_t)warp * 128 + lane * 4) = acc;
}

__global__ void agg_d64_kernel(const float* __restrict__ bias,
                               float* out_ext, int out_id, int do_relu) {
    int warp = (blockIdx.x * blockDim.x + threadIdx.x) >> 5;
    int lane = threadIdx.x & 31;
    if (warp >= NN) return;
    float* out = out_ext ? out_ext : bufptr(out_id);
    int rs = g_rowptr[warp], re = g_rowptr[warp + 1];
    float di = g_din[warp];
    float sc = di * di;
    float2 acc = *reinterpret_cast<const float2*>(g_h + (size_t)warp * 64 + lane * 2);
    acc.x *= sc; acc.y *= sc;
    for (int j = rs; j < re; j++) {
        int s = g_ssrc[j];
        float c = g_scoef[j];
        float2 v = *reinterpret_cast<const float2*>(g_h + (size_t)s * 64 + lane * 2);
        acc.x += v.x * c; acc.y += v.y * c;
    }
    float2 b = *reinterpret_cast<const float2*>(bias + lane * 2);
    acc.x += b.x; acc.y += b.y;
    if (do_relu) { acc.x = fmaxf(acc.x, 0.0f); acc.y = fmaxf(acc.y, 0.0f); }
    *reinterpret_cast<float2*>(out + (size_t)warp * 64 + lane * 2) = acc;
}

// ---------------- BF16x3 tensor-core GEMM ------------------------------------
// C[N,M] = A[N,K] @ B[K,M] (+bias)(+relu)
// block tile 128x64, 8 warps (4 m x 2 n), warp tile 32x32, BK=16 (one k16 mma).
// bf16 hi/lo split precomputed into smem at tile-load; register prefetch.
// mma m16n8k16: 2x MAC density of tf32 k8 -> half the mma instructions.
#define GBM 128
#define GBN 64
#define GBK 16
#define AK2 8     // k-pairs per A row
#define APAD 4    // A stride 12 u32: banks (12g+t)%32 all distinct
#define BPAD 8    // B stride 72 u32: banks (8k+n)%32 all distinct

// split f0,f1 -> packed bf16x2 hi and lo ((f0 low, f1 high))
__device__ __forceinline__ void splitbf2(float f0, float f1, uint32_t& hi, uint32_t& lo) {
    __nv_bfloat162 h = __floats2bfloat162_rn(f0, f1);
    float r0 = f0 - __bfloat162float(h.x);
    float r1 = f1 - __bfloat162float(h.y);
    __nv_bfloat162 l = __floats2bfloat162_rn(r0, r1);
    hi = *reinterpret_cast<uint32_t*>(&h);
    lo = *reinterpret_cast<uint32_t*>(&l);
}

// non-volatile: lets ptxas interleave independent mmas
__device__ __forceinline__ void mma_bf16(float c[4],
                                         uint32_t a0, uint32_t a1, uint32_t a2, uint32_t a3,
                                         uint32_t b0, uint32_t b1) {
    asm("mma.sync.aligned.m16n8k16.row.col.f32.bf16.bf16.f32 "
        "{%0,%1,%2,%3}, {%4,%5,%6,%7}, {%8,%9}, {%0,%1,%2,%3};"
        : "+f"(c[0]), "+f"(c[1]), "+f"(c[2]), "+f"(c[3])
        : "r"(a0), "r"(a1), "r"(a2), "r"(a3), "r"(b0), "r"(b1));
}

__global__ void __launch_bounds__(256, 2)
gemm_tc_kernel(const float* A_ext, int a_id,
               const float* __restrict__ B,
               const float* __restrict__ bias,
               float* C_ext, int c_id,
               int N, int K, int M, int do_relu) {
    // A: [m][k2] packed bf16x2 (k, k+1); B: [k2][n] packed bf16x2 (k, k+1)
    __shared__ uint32_t AsH[GBM][AK2 + APAD];
    __shared__ uint32_t AsL[GBM][AK2 + APAD];
    __shared__ uint32_t BsH[AK2][GBN + BPAD];
    __shared__ uint32_t BsL[AK2][GBN + BPAD];

    const float* A = A_ext ? A_ext : bufptr(a_id);
    float*       C = C_ext ? C_ext : bufptr(c_id);

    int tid  = threadIdx.x;
    int wid  = tid >> 5;
    int lane = tid & 31;
    int wm   = wid & 3;
    int wn   = wid >> 2;
    int group = lane >> 2;       // 0..7
    int tig   = lane & 3;        // 0..3

    int row0 = blockIdx.y * GBM;
    int col0 = blockIdx.x * GBN;

    float acc[2][4][4];
#pragma unroll
    for (int mi = 0; mi < 2; mi++)
#pragma unroll
        for (int ni = 0; ni < 4; ni++)
#pragma unroll
            for (int q = 0; q < 4; q++) acc[mi][ni][q] = 0.0f;

    // A: 128 rows x 16 floats = 512 float4, 2/thread.
    // B: per thread 2 packs (k2, n even/odd pair) via two float2 loads.
    auto loadTile = [&](int k0, float4 (&pa)[2], float2& pb0, float2& pb1) {
#pragma unroll
        for (int q = 0; q < 2; q++) {
            int f4 = tid * 2 + q;
            int r  = f4 >> 2;
            int c4 = (f4 & 3) * 4;
            int gr = row0 + r;
            pa[q] = (gr < N)
                  ? *reinterpret_cast<const float4*>(A + (size_t)gr * K + k0 + c4)
                  : make_float4(0.f, 0.f, 0.f, 0.f);
        }
        {
            int p  = tid * 2;           // pack index (even)
            int k2 = p >> 6;            // 0..7
            int n  = p & 63;            // even
            pb0 = *reinterpret_cast<const float2*>(B + (size_t)(k0 + 2 * k2)     * M + col0 + n);
            pb1 = *reinterpret_cast<const float2*>(B + (size_t)(k0 + 2 * k2 + 1) * M + col0 + n);
        }
    };

    auto storeTile = [&](const float4 (&pa)[2], const float2& pb0, const float2& pb1) {
#pragma unroll
        for (int q = 0; q < 2; q++) {
            int f4 = tid * 2 + q;
            int r  = f4 >> 2;
            int c2 = (f4 & 3) * 2;      // k-pair index base
            uint32_t h0, l0, h1, l1;
            splitbf2(pa[q].x, pa[q].y, h0, l0);
            splitbf2(pa[q].z, pa[q].w, h1, l1);
            AsH[r][c2 + 0] = h0; AsH[r][c2 + 1] = h1;
            AsL[r][c2 + 0] = l0; AsL[r][c2 + 1] = l1;
        }
        {
            int p  = tid * 2;
            int k2 = p >> 6;
            int n  = p & 63;
            uint32_t h0, l0, h1, l1;
            splitbf2(pb0.x, pb1.x, h0, l0);   // pack (k, k+1) at column n
            splitbf2(pb0.y, pb1.y, h1, l1);   // at column n+1
            BsH[k2][n] = h0; BsH[k2][n + 1] = h1;
            BsL[k2][n] = l0; BsL[k2][n + 1] = l1;
        }
    };

    auto compute = [&]() {
        uint32_t ahi[2][4], alo[2][4];
        uint32_t bhi[4][2], blo[4][2];
#pragma unroll
        for (int mi = 0; mi < 2; mi++) {
            int m = wm * 32 + mi * 16 + group;
            ahi[mi][0] = AsH[m    ][tig];
            ahi[mi][1] = AsH[m + 8][tig];
            ahi[mi][2] = AsH[m    ][tig + 4];
            ahi[mi][3] = AsH[m + 8][tig + 4];
            alo[mi][0] = AsL[m    ][tig];
            alo[mi][1] = AsL[m + 8][tig];
            alo[mi][2] = AsL[m    ][tig + 4];
            alo[mi][3] = AsL[m + 8][tig + 4];
        }
#pragma unroll
        for (int ni = 0; ni < 4; ni++) {
            int n = wn * 32 + ni * 8 + group;
            bhi[ni][0] = BsH[tig    ][n];
            bhi[ni][1] = BsH[tig + 4][n];
            blo[ni][0] = BsL[tig    ][n];
            blo[ni][1] = BsL[tig + 4][n];
        }
        // pass 1: HH over 8 independent accumulators
#pragma unroll
        for (int ni = 0; ni < 4; ni++)
#pragma unroll
            for (int mi = 0; mi < 2; mi++)
                mma_bf16(acc[mi][ni], ahi[mi][0], ahi[mi][1], ahi[mi][2], ahi[mi][3],
                         bhi[ni][0], bhi[ni][1]);
        // pass 2: HL
#pragma unroll
        for (int ni = 0; ni < 4; ni++)
#pragma unroll
            for (int mi = 0; mi < 2; mi++)
                mma_bf16(acc[mi][ni], ahi[mi][0], ahi[mi][1], ahi[mi][2], ahi[mi][3],
                         blo[ni][0], blo[ni][1]);
        // pass 3: LH
#pragma unroll
        for (int ni = 0; ni < 4; ni++)
#pragma unroll
            for (int mi = 0; mi < 2; mi++)
                mma_bf16(acc[mi][ni], alo[mi][0], alo[mi][1], alo[mi][2], alo[mi][3],
                         bhi[ni][0], bhi[ni][1]);
    };

    // prologue: tile 0
    float4 pa[2]; float2 pb0, pb1;
    loadTile(0, pa, pb0, pb1);
    storeTile(pa, pb0, pb1);
    __syncthreads();

    // main loop with register prefetch
    for (int k0 = GBK; k0 < K; k0 += GBK) {
        float4 na[2]; float2 nb0, nb1;
        loadTile(k0, na, nb0, nb1);
        compute();
        __syncthreads();
        storeTile(na, nb0, nb1);
        __syncthreads();
    }
    compute();

    // ---- epilogue ----
#pragma unroll
    for (int mi = 0; mi < 2; mi++) {
#pragma unroll
        for (int ni = 0; ni < 4; ni++) {
            int colb = col0 + wn * 32 + ni * 8 + tig * 2;
            float b0 = 0.f, b1 = 0.f;
            if (bias) { b0 = bias[colb]; b1 = bias[colb + 1]; }
#pragma unroll
            for (int half = 0; half < 2; half++) {
                int r = row0 + wm * 32 + mi * 16 + group + half * 8;
                if (r >= N) continue;
                float v0 = acc[mi][ni][half * 2 + 0] + b0;
                float v1 = acc[mi][ni][half * 2 + 1] + b1;
                if (do_relu) { v0 = fmaxf(v0, 0.f); v1 = fmaxf(v1, 0.f); }
                float2 vv = make_float2(v0, v1);
                *reinterpret_cast<float2*>(C + (size_t)r * M + colb) = vv;
            }
        }
    }
}

// ---------------- orchestration ----------------------------------------------
static inline void run_gemm(const float* A_ext, int a_id, const float* B,
                            const float* bias, float* C_ext, int c_id,
                            int n, int K, int M, int relu) {
    dim3 grid(M / GBN, (n + GBM - 1) / GBM);
    gemm_tc_kernel<<<grid, 256>>>(A_ext, a_id, B, bias, C_ext, c_id, n, K, M, relu);
}

static inline void run_agg128(const float* b, float* out_ext, int out_id, int relu) {
    int blocks = (NN + 7) / 8;
    agg_d128_kernel<<<blocks, 256>>>(b, out_ext, out_id, relu);
}

static inline void run_agg64(const float* b, float* out_ext, int out_id, int relu) {
    int blocks = (NN + 7) / 8;
    agg_d64_kernel<<<blocks, 256>>>(b, out_ext, out_id, relu);
}

extern "C" void kernel_launch(void* const* d_in, const int* in_sizes, int n_in,
                              void* d_out, int out_size) {
    const float* x   = (const float*)d_in[0];
    const void*  ei  = d_in[1];
    const float* W1  = (const float*)d_in[2];
    const float* b1  = (const float*)d_in[3];
    const float* W2  = (const float*)d_in[4];
    const float* b2  = (const float*)d_in[5];
    const float* W3  = (const float*)d_in[6];
    const float* b3  = (const float*)d_in[7];
    const float* Wd1 = (const float*)d_in[8];
    const float* bd1 = (const float*)d_in[9];
    const float* Wd2 = (const float*)d_in[10];
    const float* bd2 = (const float*)d_in[11];

    float* z    = (float*)d_out;                     // [N, 64]
    float* xhat = (float*)d_out + (size_t)NN * DE;   // [N, 256]

    // ---- graph preprocessing: dtype convert + CSR build -----------------
    detect_kernel<<<1, 32>>>((const int*)ei);
    zero_cnt_kernel<<<(NN + 255) / 256, 256>>>();
    convert_kernel<<<(2 * EE + 255) / 256, 256>>>(ei);
    scan1_kernel<<<NB, 1024>>>();                       // scan + dinv (fused)
    scan2_kernel<<<1, 32>>>();
    scan3_kernel<<<(NN + 255) / 256, 256>>>();          // rowptr final + cur (fused)
    fill_csr_kernel<<<(EE + 255) / 256, 256>>>();

    // ---- layer 1: h1 = relu(gcn(x, W1, b1)) -----------------------------
    run_gemm(x, -1, W1, nullptr, nullptr, 0, NN, DIN, DH, 0);   // g_h = x@W1
    run_agg128(b1, nullptr, 2, 1);                              // -> g_h1

    // ---- layer 2: h2 = relu(gcn(h1, W2, b2)) ----------------------------
    run_gemm(nullptr, 2, W2, nullptr, nullptr, 0, NN, DH, DH, 0);
    run_agg128(b2, nullptr, 2, 1);

    // ---- layer 3: z = gcn(h2, W3, b3) -----------------------------------
    run_gemm(nullptr, 2, W3, nullptr, nullptr, 0, NN, DH, DE, 0);
    run_agg64(b3, z, -1, 0);

    // ---- decoder: x_hat = relu(z@Wd1+bd1)@Wd2 + bd2 ---------------------
    run_gemm(z, -1, Wd1, bd1, nullptr, 2, NN, DE, DH, 1);
    run_gemm(nullptr, 2, Wd2, bd2, xhat, -1, NN, DH, DIN, 0);
}